// round 11
// baseline (speedup 1.0000x reference)
#include <cuda_runtime.h>
#include <cuda_bf16.h>

// Problem constants (from reference)
#define GX 352
#define GY 400
#define GZ 1
#define BSZ 4
#define NSEG (BSZ * GZ * GY * GX)   // 563200
#define NPTS 2000000
#define CH 4

// Scratch accumulators. Zero at module load; finalize_kernel re-zeroes them
// every call, so each replay's scatter finds them zeroed -> no zero node.
__device__ float4 g_sums[NSEG];
__device__ float4 g_counts4[NSEG / 4];

// Output layout: [ mean: NSEG*4 f32 ][ counts: NSEG f32 ]

// ---- Phase 1: scatter into scratch.
// PDL: launches + prefetches while the PREVIOUS replay's finalize still runs;
// GridDependencySynchronize guarantees its zeroing is complete before REDs. ----
__global__ void __launch_bounds__(256)
scatter_kernel(const float4* __restrict__ feats,
               const int4* __restrict__ coors) {
    int i = blockIdx.x * blockDim.x + threadIdx.x;
    int4  c;
    float4 f;
    bool valid = (i < NPTS);
    if (valid) {
        c = coors[i];                                 // independent of scratch
        f = feats[i];
    }
    cudaTriggerProgrammaticLaunchCompletion();        // all-CTA trigger ~= last wave
    cudaGridDependencySynchronize();                  // prev finalize fully done
    if (valid) {
        int seg = ((c.x * GZ + c.y) * GY + c.z) * GX + c.w;
        atomicAdd(&g_sums[seg], f);                   // RED.128 (L2-resident)
        atomicAdd(((float*)g_counts4) + seg, 1.0f);   // RED.32
    }
}

// ---- Phase 2: drain scratch -> out (mean + counts), re-zero scratch.
// Fully float4-vectorized: 4 segments/thread, 5 loads + 10 stores. ----
__global__ void __launch_bounds__(256)
finalize_kernel(float* __restrict__ out) {
    int t = blockIdx.x * blockDim.x + threadIdx.x;
    cudaGridDependencySynchronize();                  // all REDs visible
    if (t >= NSEG / 4) return;

    float4* mean_out   = (float4*)out;                        // NSEG float4
    float4* count_out4 = (float4*)(out + (size_t)NSEG * CH);  // NSEG/4 float4

    const float4 z = make_float4(0.f, 0.f, 0.f, 0.f);
    int base = t * 4;

    float4 cnt = g_counts4[t];
    float4 v0 = g_sums[base + 0];
    float4 v1 = g_sums[base + 1];
    float4 v2 = g_sums[base + 2];
    float4 v3 = g_sums[base + 3];

    // re-zero scratch for the next replay
    g_counts4[t]     = z;
    g_sums[base + 0] = z;
    g_sums[base + 1] = z;
    g_sums[base + 2] = z;
    g_sums[base + 3] = z;

    float i0 = 1.0f / fmaxf(cnt.x, 1.0f);
    float i1 = 1.0f / fmaxf(cnt.y, 1.0f);
    float i2 = 1.0f / fmaxf(cnt.z, 1.0f);
    float i3 = 1.0f / fmaxf(cnt.w, 1.0f);

    v0.x *= i0; v0.y *= i0; v0.z *= i0; v0.w *= i0;
    v1.x *= i1; v1.y *= i1; v1.z *= i1; v1.w *= i1;
    v2.x *= i2; v2.y *= i2; v2.z *= i2; v2.w *= i2;
    v3.x *= i3; v3.y *= i3; v3.z *= i3; v3.w *= i3;

    mean_out[base + 0] = v0;
    mean_out[base + 1] = v1;
    mean_out[base + 2] = v2;
    mean_out[base + 3] = v3;
    count_out4[t]      = cnt;
}

static inline void launch_pdl(void* func, dim3 grid, dim3 block,
                              void** args, bool pdl) {
    cudaLaunchConfig_t cfg = {};
    cfg.gridDim = grid;
    cfg.blockDim = block;
    cfg.dynamicSmemBytes = 0;
    cfg.stream = 0;                                   // capture (legacy) stream
    cudaLaunchAttribute attr[1];
    if (pdl) {
        attr[0].id = cudaLaunchAttributeProgrammaticStreamSerialization;
        attr[0].val.programmaticStreamSerializationAllowed = 1;
        cfg.attrs = attr;
        cfg.numAttrs = 1;
    }
    cudaLaunchKernelExC(&cfg, func, args);
}

extern "C" void kernel_launch(void* const* d_in, const int* in_sizes, int n_in,
                              void* d_out, int out_size) {
    const float4* feats = (const float4*)d_in[0];     // (NPTS, 4) f32
    const int4*   coors = (const int4*)d_in[1];       // (NPTS, 4) i32
    float* out = (float*)d_out;

    // 1) scatter (PDL: overlaps previous replay's finalize)
    {
        void* args[] = { (void*)&feats, (void*)&coors };
        int blocks = (NPTS + 255) / 256;
        launch_pdl((void*)scatter_kernel, dim3(blocks), dim3(256), args, true);
    }

    // 2) finalize: mean+counts to out, scratch back to zero
    //    (PDL: launch overlaps scatter tail)
    {
        void* args[] = { &out };
        int blocks = ((NSEG / 4) + 255) / 256;        // 550
        launch_pdl((void*)finalize_kernel, dim3(blocks), dim3(256), args, true);
    }
}

// round 12
// speedup vs baseline: 1.1317x; 1.1317x over previous
#include <cuda_runtime.h>
#include <cuda_bf16.h>

// Problem constants (from reference)
#define GX 352
#define GY 400
#define GZ 1
#define BSZ 4
#define NSEG (BSZ * GZ * GY * GX)   // 563200
#define NPTS 2000000
#define CH 4

// Output layout: [ mean: NSEG*4 f32 ][ counts: NSEG f32 ]

// ---- Phase 0: zero output (704000 float4s).
// 296 CTAs = 2/SM: the WHOLE grid is resident from cycle 0, so early-launched
// scatter CTAs (PDL) can only fill spare slots and spin — they cannot displace
// any zero work (fixes R8's starvation). Trigger at TOP => scatter launches,
// loads its 64MB point stream concurrently with this fill. ----
#define ZBLK 296
#define ZTHR 256
__global__ void __launch_bounds__(ZTHR)
zero_kernel(float4* __restrict__ out4) {
    cudaTriggerProgrammaticLaunchCompletion();        // release scatter launch NOW
    const int n4 = (NSEG * CH + NSEG) / 4;            // 704000
    const int stride = ZBLK * ZTHR;                   // 75776
    int i = blockIdx.x * ZTHR + threadIdx.x;
    const float4 z = make_float4(0.f, 0.f, 0.f, 0.f);
#pragma unroll 4
    for (; i < n4; i += stride)
        out4[i] = z;
}

// ---- Phase 1: scatter. Loads issued BEFORE the grid-dependency sync so the
//      DRAM stream overlaps the zero fill; REDs only after zero grid completes. ----
__global__ void __launch_bounds__(256)
scatter_kernel(const float4* __restrict__ feats,
               const int4* __restrict__ coors,
               float4* __restrict__ sums,
               float* __restrict__ counts) {
    int i = blockIdx.x * blockDim.x + threadIdx.x;
    int4  c;
    float4 f;
    bool valid = (i < NPTS);
    if (valid) {
        c = coors[i];                                 // independent of bins
        f = feats[i];
    }
    cudaTriggerProgrammaticLaunchCompletion();        // all-CTA trigger ~= last wave
    cudaGridDependencySynchronize();                  // zero grid fully done
    if (valid) {
        int seg = ((c.x * GZ + c.y) * GY + c.z) * GX + c.w;
        atomicAdd(&sums[seg], f);                     // RED.128 (L2-resident)
        atomicAdd(&counts[seg], 1.0f);                // RED.32
    }
}

// ---- Phase 2: in-place mean = sums / max(count,1) ----
__global__ void __launch_bounds__(256)
finalize_kernel(float4* __restrict__ sums,
                const float* __restrict__ counts) {
    int s = blockIdx.x * blockDim.x + threadIdx.x;
    cudaGridDependencySynchronize();                  // all REDs visible
    if (s >= NSEG) return;
    float cnt = counts[s];
    float inv = 1.0f / fmaxf(cnt, 1.0f);
    float4 v = sums[s];
    v.x *= inv; v.y *= inv; v.z *= inv; v.w *= inv;
    sums[s] = v;
}

static inline void launch_pdl(void* func, dim3 grid, dim3 block,
                              void** args, bool pdl) {
    cudaLaunchConfig_t cfg = {};
    cfg.gridDim = grid;
    cfg.blockDim = block;
    cfg.dynamicSmemBytes = 0;
    cfg.stream = 0;                                   // capture (legacy) stream
    cudaLaunchAttribute attr[1];
    if (pdl) {
        attr[0].id = cudaLaunchAttributeProgrammaticStreamSerialization;
        attr[0].val.programmaticStreamSerializationAllowed = 1;
        cfg.attrs = attr;
        cfg.numAttrs = 1;
    }
    cudaLaunchKernelExC(&cfg, func, args);
}

extern "C" void kernel_launch(void* const* d_in, const int* in_sizes, int n_in,
                              void* d_out, int out_size) {
    const float4* feats = (const float4*)d_in[0];     // (NPTS, 4) f32
    const int4*   coors = (const int4*)d_in[1];       // (NPTS, 4) i32
    float* out = (float*)d_out;

    float4* sums   = (float4*)out;                    // NSEG float4
    float*  counts = out + (size_t)NSEG * CH;         // NSEG floats

    // 0) zero output: fully-resident single wave, trigger-at-top
    {
        float4* out4 = (float4*)out;
        void* args[] = { &out4 };
        launch_pdl((void*)zero_kernel, dim3(ZBLK), dim3(ZTHR), args, false);
    }

    // 1) scatter (PDL: launch + 64MB prefetch overlap the zero fill)
    {
        void* args[] = { (void*)&feats, (void*)&coors, &sums, &counts };
        int blocks = (NPTS + 255) / 256;
        launch_pdl((void*)scatter_kernel, dim3(blocks), dim3(256), args, true);
    }

    // 2) finalize (PDL: launch overlaps scatter tail)
    {
        void* args[] = { &sums, &counts };
        int blocks = (NSEG + 255) / 256;
        launch_pdl((void*)finalize_kernel, dim3(blocks), dim3(256), args, true);
    }
}